// round 14
// baseline (speedup 1.0000x reference)
#include <cuda_runtime.h>
#include <cuda_fp16.h>
#include <cstdint>

// ---------------- problem constants ----------------
#define T_TOKENS 8192
#define HID      2048
#define NEXP     8
#define EDIM     1408
#define N1       (2*EDIM)            // 2816
#define NPAIR    (T_TOKENS*2)        // 16384
#define MAXTILES 136

// ---------------- GEMM tile config (R10 geometry) ----------------
constexpr int BM = 128, BN = 128, BK = 64, STAGES = 3;
constexpr int A_ST = BM * BK;              // halves per A stage (8192)
constexpr int B_ST = BK * BN;              // halves per B stage (8192)
constexpr int STG  = A_ST + B_ST;          // halves per stage (16384)
constexpr int SMEM_BYTES = STAGES * STG * 2;  // 98304

// ---------------- device scratch (static; no allocs) ----------------
__device__ __align__(16) __half g_x16 [(size_t)T_TOKENS * HID];        // 33.5 MB
__device__ __align__(16) __half g_up16[(size_t)NEXP * HID * N1];       // 92.3 MB [e][k][n]
__device__ __align__(16) __half g_dn16[(size_t)NEXP * EDIM * HID];     // 46.1 MB [e][k][n]
__device__ __align__(16) __half g_a   [(size_t)(NPAIR + 128) * EDIM];  // 46.4 MB (padded rows)
__device__ int    g_row_token[NPAIR + 128];
__device__ float  g_row_w   [NPAIR + 128];
__device__ int    g_cnt[NEXP];
__device__ int    g_cur[NEXP];
__device__ int    g_segstart[NEXP + 1];
__device__ int    g_tile_e   [MAXTILES];
__device__ int    g_tile_row0[MAXTILES];
__device__ int    g_tile_rows[MAXTILES];
__device__ int    g_is64;   // 1 if expert_indices buffer is int64, 0 if int32

// ---------------- PTX helpers ----------------
__device__ __forceinline__ void cp16(uint32_t dst, const void* src, int srcsz) {
    asm volatile("cp.async.cg.shared.global [%0], [%1], 16, %2;\n"
                 :: "r"(dst), "l"(src), "r"(srcsz));
}
__device__ __forceinline__ void cp_commit() { asm volatile("cp.async.commit_group;\n"); }
__device__ __forceinline__ void ldsm4(uint32_t& r0, uint32_t& r1, uint32_t& r2, uint32_t& r3, uint32_t a) {
    asm volatile("ldmatrix.sync.aligned.m8n8.x4.shared.b16 {%0,%1,%2,%3}, [%4];"
                 : "=r"(r0), "=r"(r1), "=r"(r2), "=r"(r3) : "r"(a));
}
__device__ __forceinline__ void ldsm4t(uint32_t& r0, uint32_t& r1, uint32_t& r2, uint32_t& r3, uint32_t a) {
    asm volatile("ldmatrix.sync.aligned.m8n8.x4.trans.shared.b16 {%0,%1,%2,%3}, [%4];"
                 : "=r"(r0), "=r"(r1), "=r"(r2), "=r"(r3) : "r"(a));
}
__device__ __forceinline__ void mma16816(float* d, const uint32_t* a, const uint32_t* b) {
    asm volatile("mma.sync.aligned.m16n8k16.row.col.f32.f16.f16.f32 "
                 "{%0,%1,%2,%3}, {%4,%5,%6,%7}, {%8,%9}, {%0,%1,%2,%3};"
                 : "+f"(d[0]), "+f"(d[1]), "+f"(d[2]), "+f"(d[3])
                 : "r"(a[0]), "r"(a[1]), "r"(a[2]), "r"(a[3]), "r"(b[0]), "r"(b[1]));
}

// read expert index p under either dtype
__device__ __forceinline__ int read_eidx(const void* idx, int p) {
    if (g_is64) return (int)((const long long*)idx)[p];
    return ((const int*)idx)[p];
}

// ---------------- conversion kernels ----------------
__device__ __forceinline__ void cvt4(const float4* __restrict__ s, __half2* __restrict__ d, int i) {
    float4 v = s[i];
    d[2*i]   = __floats2half2_rn(v.x, v.y);
    d[2*i+1] = __floats2half2_rn(v.z, v.w);
}
__global__ void k_cvt_x (const float4* __restrict__ s) { cvt4(s, (__half2*)g_x16,  blockIdx.x*256 + threadIdx.x); }
__global__ void k_cvt_up(const float4* __restrict__ s) { cvt4(s, (__half2*)g_up16, blockIdx.x*256 + threadIdx.x); }
__global__ void k_cvt_dn(const float4* __restrict__ s) { cvt4(s, (__half2*)g_dn16, blockIdx.x*256 + threadIdx.x); }

// ---------------- routing kernels ----------------
__global__ void k_route_init(const int* __restrict__ idx_words) {
    int t = threadIdx.x;
    if (t < NEXP) g_cnt[t] = 0;
    if (t == 0) {
        int any = 0;
        for (int i = 1; i < 256; i += 2) any |= idx_words[i];
        g_is64 = (any == 0) ? 1 : 0;
    }
}
__global__ void k_count(const void* __restrict__ idx) {
    int p = blockIdx.x * 256 + threadIdx.x;
    atomicAdd(&g_cnt[read_eidx(idx, p)], 1);
}
__global__ void k_scan() {
    int s = 0;
    for (int e = 0; e < NEXP; e++) { g_segstart[e] = s; s += g_cnt[e]; g_cur[e] = 0; }
    g_segstart[NEXP] = s;
    int t = 0;
    for (int e = 0; e < NEXP; e++) {
        int c = g_cnt[e];
        for (int off = 0; off < c; off += BM) {
            g_tile_e[t] = e;
            g_tile_row0[t] = g_segstart[e] + off;
            int rem = c - off;
            g_tile_rows[t] = rem < BM ? rem : BM;
            t++;
        }
    }
    for (; t < MAXTILES; t++) { g_tile_e[t] = -1; g_tile_row0[t] = 0; g_tile_rows[t] = 0; }
    for (int r = NPAIR; r < NPAIR + 128; r++) { g_row_token[r] = 0; g_row_w[r] = 0.f; }
}
__global__ void k_scatter(const void* __restrict__ idx, const float* __restrict__ sc) {
    int p = blockIdx.x * 256 + threadIdx.x;
    int e = read_eidx(idx, p);
    int slot = atomicAdd(&g_cur[e], 1);
    int r = g_segstart[e] + slot;
    g_row_token[r] = p >> 1;
    g_row_w[r] = sc[p];
}

// ---------------- fused MoE GEMM (fp16 mma.sync, 3-stage cp.async) ----------------
// Mainloop is byte-for-byte R10. Only deltas (vs R10), both outside the loop:
// G1: B tile interleaves 8-col gate/up blocks (cn even -> gate col n0+(cn>>1)*8,
//     odd -> up col EDIM+n0+(cn>>1)*8, n0 = blockIdx.x*64); epilogue computes
//     a = silu(gate)*up in-register, writes fp16 g_a (64 output cols/CTA).
// G2: UNCHANGED from R10 (atomicAdd of w*y into out; memset'ed d_out).
template<int KIT, int LDB, bool G1>
__global__ void __launch_bounds__(256, 1) moe_gemm(float* __restrict__ out) {
    int tile = blockIdx.y;
    int te = g_tile_e[tile];
    if (te < 0) return;
    int row0  = g_tile_row0[tile];
    int trows = g_tile_rows[tile];
    const __half* Bexp = (G1 ? g_up16 : g_dn16) + (size_t)te * (size_t)(KIT * BK) * LDB;

    extern __shared__ __half smem[];
    uint32_t sbase = (uint32_t)__cvta_generic_to_shared(smem);
    int tid = threadIdx.x;

    // per-thread load assignments (fixed across k-iterations)
    const __half* a_src[4]; uint32_t a_dst[4]; int a_sz[4];
    const __half* b_src[4]; uint32_t b_dst[4];
#pragma unroll
    for (int i = 0; i < 4; i++) {
        int cid = tid + i * 256;
        int m = cid >> 3, c = cid & 7;                          // A: 128 rows x 8 chunks(16B)
        a_dst[i] = sbase + (uint32_t)((m * 64 + ((c ^ (m & 7)) << 3)) * 2);
        if (G1) {
            int tok = g_row_token[row0 + m];
            a_src[i] = g_x16 + (size_t)tok * HID + c * 8;
            a_sz[i] = (m < trows) ? 16 : 0;                     // zero-fill pad rows
        } else {
            a_src[i] = g_a + (size_t)(row0 + m) * EDIM + c * 8; // padded scratch, in-bounds
            a_sz[i] = 16;
        }
        int k = cid >> 4, cn = cid & 15;                        // B: 64 rows x 16 chunks(16B)
        b_dst[i] = sbase + (uint32_t)((A_ST + k * 128 + ((cn ^ (k & 7)) << 3)) * 2);
        int col;
        if (G1) {
            int n0 = blockIdx.x * 64;                           // output col base (gate index)
            col = ((cn & 1) ? EDIM : 0) + n0 + (cn >> 1) * 8;
        } else {
            col = blockIdx.x * 128 + cn * 8;
        }
        b_src[i] = Bexp + (size_t)k * LDB + col;
    }

    auto load_tile = [&](int stage, int kt) {
        uint32_t soff = (uint32_t)(stage * STG * 2);
        int k0 = kt * BK;
#pragma unroll
        for (int i = 0; i < 4; i++) cp16(a_dst[i] + soff, a_src[i] + k0, a_sz[i]);
#pragma unroll
        for (int i = 0; i < 4; i++) cp16(b_dst[i] + soff, b_src[i] + (size_t)k0 * LDB, 16);
    };

    int lane = tid & 31, warp = tid >> 5;
    int wm = (warp & 3) * 32;      // 4 warps along M
    int wn = (warp >> 2) * 64;     // 2 warps along tile-N
    int lr = lane & 15, lc = lane >> 4;

    float acc[2][8][4];
#pragma unroll
    for (int im = 0; im < 2; im++)
#pragma unroll
        for (int j = 0; j < 8; j++)
#pragma unroll
            for (int q = 0; q < 4; q++) acc[im][j][q] = 0.f;

    auto compute_stage = [&](int stage) {
        uint32_t abase = sbase + (uint32_t)(stage * STG * 2);
        uint32_t bbase = abase + A_ST * 2;
#pragma unroll
        for (int kk = 0; kk < 4; kk++) {                 // 4 x k16 per BK=64
            uint32_t af[2][4], bf[8][2];
#pragma unroll
            for (int im = 0; im < 2; im++) {
                int m = wm + im * 16 + lr;
                int c = kk * 2 + lc;
                ldsm4(af[im][0], af[im][1], af[im][2], af[im][3],
                      abase + (uint32_t)((m * 64 + ((c ^ (m & 7)) << 3)) * 2));
            }
#pragma unroll
            for (int jn = 0; jn < 4; jn++) {
                int k = kk * 16 + lr;
                int c = ((wn + jn * 16) >> 3) + lc;
                ldsm4t(bf[2*jn][0], bf[2*jn][1], bf[2*jn+1][0], bf[2*jn+1][1],
                       bbase + (uint32_t)((k * 128 + ((c ^ (k & 7)) << 3)) * 2));
            }
#pragma unroll
            for (int im = 0; im < 2; im++)
#pragma unroll
                for (int j = 0; j < 8; j++)
                    mma16816(acc[im][j], af[im], bf[j]);
        }
    };

    // pipeline: prologue loads stages 0,1 (R10-proven structure)
    load_tile(0, 0); cp_commit();
    load_tile(1, 1); cp_commit();
#pragma unroll 1
    for (int kt = 0; kt < KIT; ++kt) {
        asm volatile("cp.async.wait_group 1;\n" ::: "memory");
        __syncthreads();
        if (kt + 2 < KIT) load_tile((kt + 2) % STAGES, kt + 2);
        cp_commit();
        compute_stage(kt % STAGES);
    }

    // epilogue
    int lq = lane >> 2;
    int ln = (lane & 3) * 2;
    if (G1) {
        int n0 = blockIdx.x * 64;
        int wno = (warp >> 2) * 32;                    // 32 output cols per N-warp
#pragma unroll
        for (int im = 0; im < 2; im++) {
#pragma unroll
            for (int rr = 0; rr < 2; rr++) {
                int rl = wm + im * 16 + lq + rr * 8;
                if (rl < trows) {
                    __half* dst = g_a + (size_t)(row0 + rl) * EDIM + n0 + wno;
#pragma unroll
                    for (int jh = 0; jh < 4; jh++) {   // bf pairs (2jh: gate, 2jh+1: up)
                        float g0 = acc[im][2*jh  ][2*rr], g1 = acc[im][2*jh  ][2*rr+1];
                        float u0 = acc[im][2*jh+1][2*rr], u1 = acc[im][2*jh+1][2*rr+1];
                        float v0 = g0 / (1.f + __expf(-g0)) * u0;
                        float v1 = g1 / (1.f + __expf(-g1)) * u1;
                        *reinterpret_cast<__half2*>(dst + jh * 8 + ln) = __floats2half2_rn(v0, v1);
                    }
                }
            }
        }
    } else {
#pragma unroll
        for (int im = 0; im < 2; im++) {
#pragma unroll
            for (int rr = 0; rr < 2; rr++) {
                int rl = wm + im * 16 + lq + rr * 8;
                if (rl < trows) {
                    int tok = g_row_token[row0 + rl];
                    float w = g_row_w[row0 + rl];
                    float* ob = out + (size_t)tok * HID;
#pragma unroll
                    for (int j = 0; j < 8; j++) {
                        int n = blockIdx.x * 128 + wn + j * 8 + ln;
                        atomicAdd(&ob[n],     w * acc[im][j][2*rr]);
                        atomicAdd(&ob[n + 1], w * acc[im][j][2*rr + 1]);
                    }
                }
            }
        }
    }
}

// ---------------- host entry ----------------
extern "C" void kernel_launch(void* const* d_in, const int* in_sizes, int n_in,
                              void* d_out, int out_size) {
    const float* x    = (const float*)d_in[0];
    const void*  eidx = d_in[1];                 // int32 or int64 — detected on device
    const float* sc   = (const float*)d_in[2];
    const float* up   = (const float*)d_in[3];
    const float* dn   = (const float*)d_in[4];
    float*       out  = (float*)d_out;

    cudaFuncSetAttribute(moe_gemm<HID/BK,  N1,  true >, cudaFuncAttributeMaxDynamicSharedMemorySize, SMEM_BYTES);
    cudaFuncSetAttribute(moe_gemm<EDIM/BK, HID, false>, cudaFuncAttributeMaxDynamicSharedMemorySize, SMEM_BYTES);

    cudaMemsetAsync(d_out, 0, (size_t)T_TOKENS * HID * sizeof(float), 0);

    // fp32 -> fp16 conversions (native [e][k][n] weight layout)
    k_cvt_x <<<(T_TOKENS*HID)  /4/256, 256>>>((const float4*)x);
    k_cvt_up<<<(NEXP*HID*N1)   /4/256, 256>>>((const float4*)up);
    k_cvt_dn<<<(NEXP*EDIM*HID) /4/256, 256>>>((const float4*)dn);

    // routing
    k_route_init<<<1, 32>>>((const int*)eidx);
    k_count  <<<NPAIR/256, 256>>>(eidx);
    k_scan   <<<1, 1>>>();
    k_scatter<<<NPAIR/256, 256>>>(eidx, sc);

    // GEMM1 (fused SiLU): a = silu(x@up_gate) * (x@up_up), fp16  (22 x 136 CTAs)
    moe_gemm<HID/BK, N1, true><<<dim3(EDIM/64, MAXTILES), 256, SMEM_BYTES>>>(nullptr);

    // GEMM2 (R10-identical): out += w * (a @ dn[e])  (16 x 136 CTAs)
    moe_gemm<EDIM/BK, HID, false><<<dim3(HID/128, MAXTILES), 256, SMEM_BYTES>>>(out);

    (void)in_sizes; (void)n_in; (void)out_size;
}

// round 15
// speedup vs baseline: 1.6344x; 1.6344x over previous
#include <cuda_runtime.h>
#include <cuda_fp16.h>
#include <cstdint>

// ---------------- problem constants ----------------
#define T_TOKENS 8192
#define HID      2048
#define NEXP     8
#define EDIM     1408
#define N1       (2*EDIM)            // 2816
#define NPAIR    (T_TOKENS*2)        // 16384
#define MAXTILES 136

// ---------------- GEMM tile config (R10 geometry, proven 1080us) ----------------
constexpr int BM = 128, BN = 128, BK = 64, STAGES = 3;
constexpr int A_ST = BM * BK;              // halves per A stage (8192)
constexpr int B_ST = BK * BN;              // halves per B stage (8192)
constexpr int STG  = A_ST + B_ST;          // halves per stage (16384)
constexpr int SMEM_BYTES = STAGES * STG * 2;  // 98304

// ---------------- device scratch (static; no allocs) ----------------
__device__ __align__(16) __half g_x16 [(size_t)T_TOKENS * HID];        // 33.5 MB
__device__ __align__(16) __half g_up16[(size_t)NEXP * HID * N1];       // 92.3 MB [e][k][n]
__device__ __align__(16) __half g_dn16[(size_t)NEXP * EDIM * HID];     // 46.1 MB [e][k][n]
__device__ __align__(16) __half g_h16 [(size_t)NPAIR * N1];            // 92.3 MB (fp16 h)
__device__ __align__(16) __half g_a   [(size_t)(NPAIR + 128) * EDIM];  // 46.4 MB (padded rows)
__device__ int    g_row_token[NPAIR + 128];
__device__ float  g_row_w   [NPAIR + 128];
__device__ int    g_tile_e   [MAXTILES];
__device__ int    g_tile_row0[MAXTILES];
__device__ int    g_tile_rows[MAXTILES];
__device__ int    g_is64;   // 1 if expert_indices buffer is int64, 0 if int32

// ---------------- PTX helpers ----------------
__device__ __forceinline__ void cp16(uint32_t dst, const void* src, int srcsz) {
    asm volatile("cp.async.cg.shared.global [%0], [%1], 16, %2;\n"
                 :: "r"(dst), "l"(src), "r"(srcsz));
}
__device__ __forceinline__ void cp_commit() { asm volatile("cp.async.commit_group;\n"); }
__device__ __forceinline__ void ldsm4(uint32_t& r0, uint32_t& r1, uint32_t& r2, uint32_t& r3, uint32_t a) {
    asm volatile("ldmatrix.sync.aligned.m8n8.x4.shared.b16 {%0,%1,%2,%3}, [%4];"
                 : "=r"(r0), "=r"(r1), "=r"(r2), "=r"(r3) : "r"(a));
}
__device__ __forceinline__ void ldsm4t(uint32_t& r0, uint32_t& r1, uint32_t& r2, uint32_t& r3, uint32_t a) {
    asm volatile("ldmatrix.sync.aligned.m8n8.x4.trans.shared.b16 {%0,%1,%2,%3}, [%4];"
                 : "=r"(r0), "=r"(r1), "=r"(r2), "=r"(r3) : "r"(a));
}
__device__ __forceinline__ void mma16816(float* d, const uint32_t* a, const uint32_t* b) {
    asm volatile("mma.sync.aligned.m16n8k16.row.col.f32.f16.f16.f32 "
                 "{%0,%1,%2,%3}, {%4,%5,%6,%7}, {%8,%9}, {%0,%1,%2,%3};"
                 : "+f"(d[0]), "+f"(d[1]), "+f"(d[2]), "+f"(d[3])
                 : "r"(a[0]), "r"(a[1]), "r"(a[2]), "r"(a[3]), "r"(b[0]), "r"(b[1]));
}

// read expert index p under either dtype
__device__ __forceinline__ int read_eidx(const void* idx, int p) {
    if (g_is64) return (int)((const long long*)idx)[p];
    return ((const int*)idx)[p];
}

// ---------------- conversion kernels ----------------
__device__ __forceinline__ void cvt4(const float4* __restrict__ s, __half2* __restrict__ d, int i) {
    float4 v = s[i];
    d[2*i]   = __floats2half2_rn(v.x, v.y);
    d[2*i+1] = __floats2half2_rn(v.z, v.w);
}
__global__ void k_cvt_x (const float4* __restrict__ s) { cvt4(s, (__half2*)g_x16,  blockIdx.x*256 + threadIdx.x); }
__global__ void k_cvt_up(const float4* __restrict__ s) { cvt4(s, (__half2*)g_up16, blockIdx.x*256 + threadIdx.x); }
__global__ void k_cvt_dn(const float4* __restrict__ s) { cvt4(s, (__half2*)g_dn16, blockIdx.x*256 + threadIdx.x); }

// ---------------- merged routing (single block, 256 threads) ----------------
// Does dtype-detect + count + scan/tile-table + scatter in ONE launch so that
// GEMM1 lands at kernel-launch position 4 (the slot ncu has been capturing).
__global__ void k_route_all(const int* __restrict__ idx_words, const float* __restrict__ sc) {
    __shared__ int scnt[NEXP];
    __shared__ int sseg[NEXP + 1];
    __shared__ int scur[NEXP];
    int t = threadIdx.x;
    if (t == 0) {
        // int64 little-endian => every odd 32-bit word is 0 (values in [0,8))
        int any = 0;
        for (int i = 1; i < 256; i += 2) any |= idx_words[i];
        g_is64 = (any == 0) ? 1 : 0;
    }
    if (t < NEXP) { scnt[t] = 0; scur[t] = 0; }
    __syncthreads();
    const void* idx = (const void*)idx_words;
    for (int p = t; p < NPAIR; p += 256) atomicAdd(&scnt[read_eidx(idx, p)], 1);
    __syncthreads();
    if (t == 0) {
        int s = 0;
        for (int e = 0; e < NEXP; e++) { sseg[e] = s; s += scnt[e]; }
        sseg[NEXP] = s;
        int tt = 0;
        for (int e = 0; e < NEXP; e++) {
            int c = scnt[e];
            for (int off = 0; off < c; off += BM) {
                g_tile_e[tt] = e;
                g_tile_row0[tt] = sseg[e] + off;
                int rem = c - off;
                g_tile_rows[tt] = rem < BM ? rem : BM;
                tt++;
            }
        }
        for (; tt < MAXTILES; tt++) { g_tile_e[tt] = -1; g_tile_row0[tt] = 0; g_tile_rows[tt] = 0; }
        for (int r = NPAIR; r < NPAIR + 128; r++) { g_row_token[r] = 0; g_row_w[r] = 0.f; }
    }
    __syncthreads();
    for (int p = t; p < NPAIR; p += 256) {
        int e = read_eidx(idx, p);
        int slot = atomicAdd(&scur[e], 1);
        int r = sseg[e] + slot;
        g_row_token[r] = p >> 1;
        g_row_w[r] = sc[p];
    }
}

// ---------------- activation: a = silu(gate) * up (fp16 in, fp16 out) ----------------
__global__ void k_act() {
    int r = blockIdx.y;
    int j = blockIdx.x * 128 + threadIdx.x;   // grid.x = 11 -> j in [0,1408)
    size_t base = (size_t)r * N1;
    float g = __half2float(g_h16[base + j]);
    float u = __half2float(g_h16[base + EDIM + j]);
    float sv = g / (1.f + __expf(-g));
    g_a[(size_t)r * EDIM + j] = __float2half_rn(sv * u);
}

// ---------------- fused MoE GEMM (fp16 mma.sync, 3-stage cp.async) ----------------
// R10-identical mainloop and structure. Single delta vs R10: G1 epilogue stores
// h as fp16 (__half2) into g_h16 instead of fp32 into g_h. G2 unchanged (atomics).
template<int KIT, int LDB, bool G1>
__global__ void __launch_bounds__(256, 1) moe_gemm(float* __restrict__ out) {
    int tile = blockIdx.y;
    int te = g_tile_e[tile];
    if (te < 0) return;
    int row0  = g_tile_row0[tile];
    int trows = g_tile_rows[tile];
    int n0 = blockIdx.x * BN;
    const __half* Bexp = (G1 ? g_up16 : g_dn16) + (size_t)te * (size_t)(KIT * BK) * LDB;

    extern __shared__ __half smem[];
    uint32_t sbase = (uint32_t)__cvta_generic_to_shared(smem);
    int tid = threadIdx.x;

    // per-thread load assignments (fixed across k-iterations)
    const __half* a_src[4]; uint32_t a_dst[4]; int a_sz[4];
    const __half* b_src[4]; uint32_t b_dst[4];
#pragma unroll
    for (int i = 0; i < 4; i++) {
        int cid = tid + i * 256;
        int m = cid >> 3, c = cid & 7;                          // A: 128 rows x 8 chunks(16B)
        a_dst[i] = sbase + (uint32_t)((m * 64 + ((c ^ (m & 7)) << 3)) * 2);
        if (G1) {
            int tok = g_row_token[row0 + m];
            a_src[i] = g_x16 + (size_t)tok * HID + c * 8;
            a_sz[i] = (m < trows) ? 16 : 0;                     // zero-fill pad rows
        } else {
            a_src[i] = g_a + (size_t)(row0 + m) * EDIM + c * 8; // padded scratch, in-bounds
            a_sz[i] = 16;
        }
        int k = cid >> 4, cn = cid & 15;                        // B: 64 rows x 16 chunks(16B)
        b_dst[i] = sbase + (uint32_t)((A_ST + k * 128 + ((cn ^ (k & 7)) << 3)) * 2);
        b_src[i] = Bexp + (size_t)k * LDB + n0 + cn * 8;
    }

    auto load_tile = [&](int stage, int kt) {
        uint32_t soff = (uint32_t)(stage * STG * 2);
        int k0 = kt * BK;
#pragma unroll
        for (int i = 0; i < 4; i++) cp16(a_dst[i] + soff, a_src[i] + k0, a_sz[i]);
#pragma unroll
        for (int i = 0; i < 4; i++) cp16(b_dst[i] + soff, b_src[i] + (size_t)k0 * LDB, 16);
    };

    int lane = tid & 31, warp = tid >> 5;
    int wm = (warp & 3) * 32;      // 4 warps along M
    int wn = (warp >> 2) * 64;     // 2 warps along N
    int lr = lane & 15, lc = lane >> 4;

    float acc[2][8][4];
#pragma unroll
    for (int im = 0; im < 2; im++)
#pragma unroll
        for (int j = 0; j < 8; j++)
#pragma unroll
            for (int q = 0; q < 4; q++) acc[im][j][q] = 0.f;

    auto compute_stage = [&](int stage) {
        uint32_t abase = sbase + (uint32_t)(stage * STG * 2);
        uint32_t bbase = abase + A_ST * 2;
#pragma unroll
        for (int kk = 0; kk < 4; kk++) {                 // 4 x k16 per BK=64
            uint32_t af[2][4], bf[8][2];
#pragma unroll
            for (int im = 0; im < 2; im++) {
                int m = wm + im * 16 + lr;
                int c = kk * 2 + lc;
                ldsm4(af[im][0], af[im][1], af[im][2], af[im][3],
                      abase + (uint32_t)((m * 64 + ((c ^ (m & 7)) << 3)) * 2));
            }
#pragma unroll
            for (int jn = 0; jn < 4; jn++) {
                int k = kk * 16 + lr;
                int c = ((wn + jn * 16) >> 3) + lc;
                ldsm4t(bf[2*jn][0], bf[2*jn][1], bf[2*jn+1][0], bf[2*jn+1][1],
                       bbase + (uint32_t)((k * 128 + ((c ^ (k & 7)) << 3)) * 2));
            }
#pragma unroll
            for (int im = 0; im < 2; im++)
#pragma unroll
                for (int j = 0; j < 8; j++)
                    mma16816(acc[im][j], af[im], bf[j]);
        }
    };

    // pipeline: prologue loads stages 0,1 (R10-proven structure)
    load_tile(0, 0); cp_commit();
    load_tile(1, 1); cp_commit();
#pragma unroll 1
    for (int kt = 0; kt < KIT; ++kt) {
        asm volatile("cp.async.wait_group 1;\n" ::: "memory");
        __syncthreads();
        if (kt + 2 < KIT) load_tile((kt + 2) % STAGES, kt + 2);
        cp_commit();
        compute_stage(kt % STAGES);
    }

    // epilogue
    int lq = lane >> 2;
    int ln = (lane & 3) * 2;
    if (G1) {
#pragma unroll
        for (int im = 0; im < 2; im++) {
#pragma unroll
            for (int rr = 0; rr < 2; rr++) {
                int rl = wm + im * 16 + lq + rr * 8;
                if (rl < trows) {
                    size_t rowb = (size_t)(row0 + rl) * N1;
#pragma unroll
                    for (int j = 0; j < 8; j++) {
                        int n = n0 + wn + j * 8 + ln;
                        *reinterpret_cast<__half2*>(&g_h16[rowb + n]) =
                            __floats2half2_rn(acc[im][j][2*rr], acc[im][j][2*rr + 1]);
                    }
                }
            }
        }
    } else {
#pragma unroll
        for (int im = 0; im < 2; im++) {
#pragma unroll
            for (int rr = 0; rr < 2; rr++) {
                int rl = wm + im * 16 + lq + rr * 8;
                if (rl < trows) {
                    int tok = g_row_token[row0 + rl];
                    float w = g_row_w[row0 + rl];
                    float* ob = out + (size_t)tok * HID;
#pragma unroll
                    for (int j = 0; j < 8; j++) {
                        int n = n0 + wn + j * 8 + ln;
                        atomicAdd(&ob[n],     w * acc[im][j][2*rr]);
                        atomicAdd(&ob[n + 1], w * acc[im][j][2*rr + 1]);
                    }
                }
            }
        }
    }
}

// ---------------- host entry ----------------
extern "C" void kernel_launch(void* const* d_in, const int* in_sizes, int n_in,
                              void* d_out, int out_size) {
    const float* x    = (const float*)d_in[0];
    const void*  eidx = d_in[1];                 // int32 or int64 — detected on device
    const float* sc   = (const float*)d_in[2];
    const float* up   = (const float*)d_in[3];
    const float* dn   = (const float*)d_in[4];
    float*       out  = (float*)d_out;

    cudaFuncSetAttribute(moe_gemm<HID/BK,  N1,  true >, cudaFuncAttributeMaxDynamicSharedMemorySize, SMEM_BYTES);
    cudaFuncSetAttribute(moe_gemm<EDIM/BK, HID, false>, cudaFuncAttributeMaxDynamicSharedMemorySize, SMEM_BYTES);

    cudaMemsetAsync(d_out, 0, (size_t)T_TOKENS * HID * sizeof(float), 0);

    // Launch order puts GEMM1 at kernel position 4 (ncu capture slot).
    k_cvt_x    <<<(T_TOKENS*HID)/4/256, 256>>>((const float4*)x);        // 1
    k_cvt_up   <<<(NEXP*HID*N1) /4/256, 256>>>((const float4*)up);       // 2
    k_route_all<<<1, 256>>>((const int*)eidx, sc);                       // 3

    // GEMM1: h16 = gather(x16) @ up16[e]  (22 x 136 CTAs)                  4
    moe_gemm<HID/BK, N1, true><<<dim3(N1/BN, MAXTILES), 256, SMEM_BYTES>>>(nullptr);

    k_cvt_dn   <<<(NEXP*EDIM*HID)/4/256, 256>>>((const float4*)dn);      // 5

    // activation: a = silu(gate) * up                                      6
    k_act<<<dim3(EDIM/128, NPAIR), 128>>>();

    // GEMM2: out += w * (a @ dn16[e])  (16 x 136 CTAs)                     7
    moe_gemm<EDIM/BK, HID, false><<<dim3(HID/128, MAXTILES), 256, SMEM_BYTES>>>(out);

    (void)in_sizes; (void)n_in; (void)out_size;
}

// round 16
// speedup vs baseline: 1.9180x; 1.1735x over previous
#include <cuda_runtime.h>
#include <cuda_fp16.h>
#include <cstdint>

// ---------------- problem constants ----------------
#define T_TOKENS 8192
#define HID      2048
#define NEXP     8
#define EDIM     1408
#define N1       (2*EDIM)            // 2816
#define NPAIR    (T_TOKENS*2)        // 16384
#define MAXTILES 136

// ---------------- GEMM tile config ----------------
constexpr int BM = 128, BN = 128, BK = 64, STAGES = 3;
constexpr int A_ST = BM * BK;              // halves per A stage (8192)
constexpr int B_ST = BK * BN;              // halves per B stage (8192)
constexpr int STG  = A_ST + B_ST;          // halves per stage (16384)
constexpr int SMEM_BYTES = STAGES * STG * 2;  // 98304 -> fits 2 CTAs/SM (228KB)

// ---------------- device scratch (static; no allocs) ----------------
__device__ __align__(16) __half g_x16 [(size_t)T_TOKENS * HID];        // 33.5 MB
__device__ __align__(16) __half g_up16[(size_t)NEXP * HID * N1];       // 92.3 MB [e][k][n]
__device__ __align__(16) __half g_dn16[(size_t)NEXP * EDIM * HID];     // 46.1 MB [e][k][n]
__device__ __align__(16) __half g_h16 [(size_t)NPAIR * N1];            // 92.3 MB (fp16 h)
__device__ __align__(16) __half g_a   [(size_t)(NPAIR + 128) * EDIM];  // 46.4 MB (padded rows)
__device__ int    g_row_token[NPAIR + 128];
__device__ float  g_row_w   [NPAIR + 128];
__device__ int    g_tile_e   [MAXTILES];
__device__ int    g_tile_row0[MAXTILES];
__device__ int    g_tile_rows[MAXTILES];
__device__ int    g_is64;   // 1 if expert_indices buffer is int64, 0 if int32

// ---------------- PTX helpers ----------------
__device__ __forceinline__ void cp16(uint32_t dst, const void* src) {
    asm volatile("cp.async.cg.shared.global [%0], [%1], 16;\n" :: "r"(dst), "l"(src));
}
__device__ __forceinline__ void cp_commit() { asm volatile("cp.async.commit_group;\n"); }
__device__ __forceinline__ void ldsm4(uint32_t& r0, uint32_t& r1, uint32_t& r2, uint32_t& r3, uint32_t a) {
    asm volatile("ldmatrix.sync.aligned.m8n8.x4.shared.b16 {%0,%1,%2,%3}, [%4];"
                 : "=r"(r0), "=r"(r1), "=r"(r2), "=r"(r3) : "r"(a));
}
__device__ __forceinline__ void ldsm4t(uint32_t& r0, uint32_t& r1, uint32_t& r2, uint32_t& r3, uint32_t a) {
    asm volatile("ldmatrix.sync.aligned.m8n8.x4.trans.shared.b16 {%0,%1,%2,%3}, [%4];"
                 : "=r"(r0), "=r"(r1), "=r"(r2), "=r"(r3) : "r"(a));
}
__device__ __forceinline__ void mma16816(float* d, const uint32_t* a, const uint32_t* b) {
    asm volatile("mma.sync.aligned.m16n8k16.row.col.f32.f16.f16.f32 "
                 "{%0,%1,%2,%3}, {%4,%5,%6,%7}, {%8,%9}, {%0,%1,%2,%3};"
                 : "+f"(d[0]), "+f"(d[1]), "+f"(d[2]), "+f"(d[3])
                 : "r"(a[0]), "r"(a[1]), "r"(a[2]), "r"(a[3]), "r"(b[0]), "r"(b[1]));
}

// read expert index p under either dtype
__device__ __forceinline__ int read_eidx(const void* idx, int p) {
    if (g_is64) return (int)((const long long*)idx)[p];
    return ((const int*)idx)[p];
}

// ---------------- conversion kernels ----------------
__device__ __forceinline__ void cvt4(const float4* __restrict__ s, __half2* __restrict__ d, int i) {
    float4 v = s[i];
    d[2*i]   = __floats2half2_rn(v.x, v.y);
    d[2*i+1] = __floats2half2_rn(v.z, v.w);
}
__global__ void k_cvt_x (const float4* __restrict__ s) { cvt4(s, (__half2*)g_x16,  blockIdx.x*256 + threadIdx.x); }
__global__ void k_cvt_up(const float4* __restrict__ s) { cvt4(s, (__half2*)g_up16, blockIdx.x*256 + threadIdx.x); }
__global__ void k_cvt_dn(const float4* __restrict__ s) { cvt4(s, (__half2*)g_dn16, blockIdx.x*256 + threadIdx.x); }

// ---------------- merged routing (single block, 256 threads) ----------------
__global__ void k_route_all(const int* __restrict__ idx_words, const float* __restrict__ sc) {
    __shared__ int scnt[NEXP];
    __shared__ int sseg[NEXP + 1];
    __shared__ int scur[NEXP];
    int t = threadIdx.x;
    if (t == 0) {
        // int64 little-endian => every odd 32-bit word is 0 (values in [0,8))
        int any = 0;
        for (int i = 1; i < 256; i += 2) any |= idx_words[i];
        g_is64 = (any == 0) ? 1 : 0;
    }
    if (t < NEXP) { scnt[t] = 0; scur[t] = 0; }
    __syncthreads();
    const void* idx = (const void*)idx_words;
    for (int p = t; p < NPAIR; p += 256) atomicAdd(&scnt[read_eidx(idx, p)], 1);
    __syncthreads();
    if (t == 0) {
        int s = 0;
        for (int e = 0; e < NEXP; e++) { sseg[e] = s; s += scnt[e]; }
        sseg[NEXP] = s;
        int tt = 0;
        for (int e = 0; e < NEXP; e++) {
            int c = scnt[e];
            for (int off = 0; off < c; off += BM) {
                g_tile_e[tt] = e;
                g_tile_row0[tt] = sseg[e] + off;
                int rem = c - off;
                g_tile_rows[tt] = rem < BM ? rem : BM;
                tt++;
            }
        }
        for (; tt < MAXTILES; tt++) { g_tile_e[tt] = -1; g_tile_row0[tt] = 0; g_tile_rows[tt] = 0; }
        for (int r = NPAIR; r < NPAIR + 128; r++) { g_row_token[r] = 0; g_row_w[r] = 0.f; }
    }
    __syncthreads();
    for (int p = t; p < NPAIR; p += 256) {
        int e = read_eidx(idx, p);
        int slot = atomicAdd(&scur[e], 1);
        int r = sseg[e] + slot;
        g_row_token[r] = p >> 1;
        g_row_w[r] = sc[p];
    }
}

// ---------------- activation: a = silu(gate) * up (fp16 in, fp16 out) ----------------
__global__ void k_act() {
    int r = blockIdx.y;
    int j = blockIdx.x * 128 + threadIdx.x;   // grid.x = 11 -> j in [0,1408)
    size_t base = (size_t)r * N1;
    float g = __half2float(g_h16[base + j]);
    float u = __half2float(g_h16[base + EDIM + j]);
    float sv = g / (1.f + __expf(-g));
    g_a[(size_t)r * EDIM + j] = __float2half_rn(sv * u);
}

// ---------------- fused MoE GEMM (fp16 mma.sync, 3-stage cp.async) ----------------
// R15-identical structure. Single-variable delta: __launch_bounds__(256, 2)
// caps regs at 128 -> 2 CTAs/SM (was 168 regs -> 1 CTA/SM, tensor pipe 56.6%).
// The a_sz zero-fill predication is removed: pad rows (rl >= trows) load valid
// token-0 / padded-scratch data and are masked in the epilogue, so always-16B
// cp.async is safe and saves registers.
template<int KIT, int LDB, bool G1>
__global__ void __launch_bounds__(256, 2) moe_gemm(float* __restrict__ out) {
    int tile = blockIdx.y;
    int te = g_tile_e[tile];
    if (te < 0) return;
    int row0  = g_tile_row0[tile];
    int trows = g_tile_rows[tile];
    int n0 = blockIdx.x * BN;
    const __half* Bexp = (G1 ? g_up16 : g_dn16) + (size_t)te * (size_t)(KIT * BK) * LDB;

    extern __shared__ __half smem[];
    uint32_t sbase = (uint32_t)__cvta_generic_to_shared(smem);
    int tid = threadIdx.x;

    // per-thread load assignments (fixed across k-iterations)
    const __half* a_src[4]; uint32_t a_dst[4];
    const __half* b_src[4]; uint32_t b_dst[4];
#pragma unroll
    for (int i = 0; i < 4; i++) {
        int cid = tid + i * 256;
        int m = cid >> 3, c = cid & 7;                          // A: 128 rows x 8 chunks(16B)
        a_dst[i] = sbase + (uint32_t)((m * 64 + ((c ^ (m & 7)) << 3)) * 2);
        if (G1) {
            int tok = g_row_token[row0 + m];                    // pad rows -> token 0, masked later
            a_src[i] = g_x16 + (size_t)tok * HID + c * 8;
        } else {
            a_src[i] = g_a + (size_t)(row0 + m) * EDIM + c * 8; // padded scratch, in-bounds
        }
        int k = cid >> 4, cn = cid & 15;                        // B: 64 rows x 16 chunks(16B)
        b_dst[i] = sbase + (uint32_t)((A_ST + k * 128 + ((cn ^ (k & 7)) << 3)) * 2);
        b_src[i] = Bexp + (size_t)k * LDB + n0 + cn * 8;
    }

    auto load_tile = [&](int stage, int kt) {
        uint32_t soff = (uint32_t)(stage * STG * 2);
        int k0 = kt * BK;
#pragma unroll
        for (int i = 0; i < 4; i++) cp16(a_dst[i] + soff, a_src[i] + k0);
#pragma unroll
        for (int i = 0; i < 4; i++) cp16(b_dst[i] + soff, b_src[i] + (size_t)k0 * LDB);
    };

    int lane = tid & 31, warp = tid >> 5;
    int wm = (warp & 3) * 32;      // 4 warps along M
    int wn = (warp >> 2) * 64;     // 2 warps along N
    int lr = lane & 15, lc = lane >> 4;

    float acc[2][8][4];
#pragma unroll
    for (int im = 0; im < 2; im++)
#pragma unroll
        for (int j = 0; j < 8; j++)
#pragma unroll
            for (int q = 0; q < 4; q++) acc[im][j][q] = 0.f;

    auto compute_stage = [&](int stage) {
        uint32_t abase = sbase + (uint32_t)(stage * STG * 2);
        uint32_t bbase = abase + A_ST * 2;
#pragma unroll
        for (int kk = 0; kk < 4; kk++) {                 // 4 x k16 per BK=64
            uint32_t af[2][4], bf[8][2];
#pragma unroll
            for (int im = 0; im < 2; im++) {
                int m = wm + im * 16 + lr;
                int c = kk * 2 + lc;
                ldsm4(af[im][0], af[im][1], af[im][2], af[im][3],
                      abase + (uint32_t)((m * 64 + ((c ^ (m & 7)) << 3)) * 2));
            }
#pragma unroll
            for (int jn = 0; jn < 4; jn++) {
                int k = kk * 16 + lr;
                int c = ((wn + jn * 16) >> 3) + lc;
                ldsm4t(bf[2*jn][0], bf[2*jn][1], bf[2*jn+1][0], bf[2*jn+1][1],
                       bbase + (uint32_t)((k * 128 + ((c ^ (k & 7)) << 3)) * 2));
            }
#pragma unroll
            for (int im = 0; im < 2; im++)
#pragma unroll
                for (int j = 0; j < 8; j++)
                    mma16816(acc[im][j], af[im], bf[j]);
        }
    };

    // pipeline: prologue loads stages 0,1
    load_tile(0, 0); cp_commit();
    load_tile(1, 1); cp_commit();
#pragma unroll 1
    for (int kt = 0; kt < KIT; ++kt) {
        asm volatile("cp.async.wait_group 1;\n" ::: "memory");
        __syncthreads();
        if (kt + 2 < KIT) load_tile((kt + 2) % STAGES, kt + 2);
        cp_commit();
        compute_stage(kt % STAGES);
    }

    // epilogue
    int lq = lane >> 2;
    int ln = (lane & 3) * 2;
    if (G1) {
#pragma unroll
        for (int im = 0; im < 2; im++) {
#pragma unroll
            for (int rr = 0; rr < 2; rr++) {
                int rl = wm + im * 16 + lq + rr * 8;
                if (rl < trows) {
                    size_t rowb = (size_t)(row0 + rl) * N1;
#pragma unroll
                    for (int j = 0; j < 8; j++) {
                        int n = n0 + wn + j * 8 + ln;
                        *reinterpret_cast<__half2*>(&g_h16[rowb + n]) =
                            __floats2half2_rn(acc[im][j][2*rr], acc[im][j][2*rr + 1]);
                    }
                }
            }
        }
    } else {
#pragma unroll
        for (int im = 0; im < 2; im++) {
#pragma unroll
            for (int rr = 0; rr < 2; rr++) {
                int rl = wm + im * 16 + lq + rr * 8;
                if (rl < trows) {
                    int tok = g_row_token[row0 + rl];
                    float w = g_row_w[row0 + rl];
                    float* ob = out + (size_t)tok * HID;
#pragma unroll
                    for (int j = 0; j < 8; j++) {
                        int n = n0 + wn + j * 8 + ln;
                        atomicAdd(&ob[n],     w * acc[im][j][2*rr]);
                        atomicAdd(&ob[n + 1], w * acc[im][j][2*rr + 1]);
                    }
                }
            }
        }
    }
}

// ---------------- host entry ----------------
extern "C" void kernel_launch(void* const* d_in, const int* in_sizes, int n_in,
                              void* d_out, int out_size) {
    const float* x    = (const float*)d_in[0];
    const void*  eidx = d_in[1];                 // int32 or int64 — detected on device
    const float* sc   = (const float*)d_in[2];
    const float* up   = (const float*)d_in[3];
    const float* dn   = (const float*)d_in[4];
    float*       out  = (float*)d_out;

    cudaFuncSetAttribute(moe_gemm<HID/BK,  N1,  true >, cudaFuncAttributeMaxDynamicSharedMemorySize, SMEM_BYTES);
    cudaFuncSetAttribute(moe_gemm<EDIM/BK, HID, false>, cudaFuncAttributeMaxDynamicSharedMemorySize, SMEM_BYTES);

    cudaMemsetAsync(d_out, 0, (size_t)T_TOKENS * HID * sizeof(float), 0);

    // Launch order puts GEMM1 at kernel position 4 (ncu capture slot).
    k_cvt_x    <<<(T_TOKENS*HID)/4/256, 256>>>((const float4*)x);        // 1
    k_cvt_up   <<<(NEXP*HID*N1) /4/256, 256>>>((const float4*)up);       // 2
    k_route_all<<<1, 256>>>((const int*)eidx, sc);                       // 3

    // GEMM1: h16 = gather(x16) @ up16[e]  (22 x 136 CTAs)                  4
    moe_gemm<HID/BK, N1, true><<<dim3(N1/BN, MAXTILES), 256, SMEM_BYTES>>>(nullptr);

    k_cvt_dn   <<<(NEXP*EDIM*HID)/4/256, 256>>>((const float4*)dn);      // 5

    // activation: a = silu(gate) * up                                      6
    k_act<<<dim3(EDIM/128, NPAIR), 128>>>();

    // GEMM2: out += w * (a @ dn16[e])  (16 x 136 CTAs)                     7
    moe_gemm<EDIM/BK, HID, false><<<dim3(HID/128, MAXTILES), 256, SMEM_BYTES>>>(out);

    (void)in_sizes; (void)n_in; (void)out_size;
}

// round 17
// speedup vs baseline: 2.0123x; 1.0492x over previous
#include <cuda_runtime.h>
#include <cuda_fp16.h>
#include <cstdint>

// ---------------- problem constants ----------------
#define T_TOKENS 8192
#define HID      2048
#define NEXP     8
#define EDIM     1408
#define N1       (2*EDIM)            // 2816
#define NPAIR    (T_TOKENS*2)        // 16384
#define MAXTILES 136

// ---------------- GEMM tile config ----------------
constexpr int BM = 128, BN = 128, BK = 64, STAGES = 3;
constexpr int A_ST = BM * BK;              // halves per A stage (8192)
constexpr int B_ST = BK * BN;              // halves per B stage (8192)
constexpr int STG  = A_ST + B_ST;          // halves per stage (16384)
constexpr int SMEM_BYTES = STAGES * STG * 2;  // 98304 -> 2 CTAs/SM

// ---------------- device scratch (static; no allocs) ----------------
__device__ __align__(16) __half g_x16 [(size_t)T_TOKENS * HID];        // 33.5 MB
__device__ __align__(16) __half g_up16[(size_t)NEXP * HID * N1];       // 92.3 MB [e][k][n]
__device__ __align__(16) __half g_dn16[(size_t)NEXP * EDIM * HID];     // 46.1 MB [e][k][n]
__device__ __align__(16) __half g_h16 [(size_t)NPAIR * N1];            // 92.3 MB (fp16 h)
__device__ __align__(16) __half g_a   [(size_t)(NPAIR + 128) * EDIM];  // 46.4 MB (padded rows)
__device__ int    g_row_token[NPAIR + 128];
__device__ float  g_row_w   [NPAIR + 128];
__device__ int    g_tile_e   [MAXTILES];
__device__ int    g_tile_row0[MAXTILES];
__device__ int    g_tile_rows[MAXTILES];
__device__ int    g_is64;   // 1 if expert_indices buffer is int64, 0 if int32

// ---------------- PTX helpers ----------------
__device__ __forceinline__ void cp16(uint32_t dst, const void* src) {
    asm volatile("cp.async.cg.shared.global [%0], [%1], 16;\n" :: "r"(dst), "l"(src));
}
__device__ __forceinline__ void cp_commit() { asm volatile("cp.async.commit_group;\n"); }
__device__ __forceinline__ void ldsm4(uint32_t& r0, uint32_t& r1, uint32_t& r2, uint32_t& r3, uint32_t a) {
    asm volatile("ldmatrix.sync.aligned.m8n8.x4.shared.b16 {%0,%1,%2,%3}, [%4];"
                 : "=r"(r0), "=r"(r1), "=r"(r2), "=r"(r3) : "r"(a));
}
__device__ __forceinline__ void ldsm4t(uint32_t& r0, uint32_t& r1, uint32_t& r2, uint32_t& r3, uint32_t a) {
    asm volatile("ldmatrix.sync.aligned.m8n8.x4.trans.shared.b16 {%0,%1,%2,%3}, [%4];"
                 : "=r"(r0), "=r"(r1), "=r"(r2), "=r"(r3) : "r"(a));
}
__device__ __forceinline__ void mma16816(float* d, const uint32_t* a, const uint32_t* b) {
    asm volatile("mma.sync.aligned.m16n8k16.row.col.f32.f16.f16.f32 "
                 "{%0,%1,%2,%3}, {%4,%5,%6,%7}, {%8,%9}, {%0,%1,%2,%3};"
                 : "+f"(d[0]), "+f"(d[1]), "+f"(d[2]), "+f"(d[3])
                 : "r"(a[0]), "r"(a[1]), "r"(a[2]), "r"(a[3]), "r"(b[0]), "r"(b[1]));
}

// read expert index p under either dtype
__device__ __forceinline__ int read_eidx(const void* idx, int p) {
    if (g_is64) return (int)((const long long*)idx)[p];
    return ((const int*)idx)[p];
}

// ---------------- conversion kernels ----------------
__device__ __forceinline__ void cvt4(const float4* __restrict__ s, __half2* __restrict__ d, int i) {
    float4 v = s[i];
    d[2*i]   = __floats2half2_rn(v.x, v.y);
    d[2*i+1] = __floats2half2_rn(v.z, v.w);
}
__global__ void k_cvt_x (const float4* __restrict__ s) { cvt4(s, (__half2*)g_x16,  blockIdx.x*256 + threadIdx.x); }
__global__ void k_cvt_up(const float4* __restrict__ s) { cvt4(s, (__half2*)g_up16, blockIdx.x*256 + threadIdx.x); }
__global__ void k_cvt_dn(const float4* __restrict__ s) { cvt4(s, (__half2*)g_dn16, blockIdx.x*256 + threadIdx.x); }

// ---------------- merged routing (single block, 256 threads) ----------------
__global__ void k_route_all(const int* __restrict__ idx_words, const float* __restrict__ sc) {
    __shared__ int scnt[NEXP];
    __shared__ int sseg[NEXP + 1];
    __shared__ int scur[NEXP];
    int t = threadIdx.x;
    if (t == 0) {
        // int64 little-endian => every odd 32-bit word is 0 (values in [0,8))
        int any = 0;
        for (int i = 1; i < 256; i += 2) any |= idx_words[i];
        g_is64 = (any == 0) ? 1 : 0;
    }
    if (t < NEXP) { scnt[t] = 0; scur[t] = 0; }
    __syncthreads();
    const void* idx = (const void*)idx_words;
    for (int p = t; p < NPAIR; p += 256) atomicAdd(&scnt[read_eidx(idx, p)], 1);
    __syncthreads();
    if (t == 0) {
        int s = 0;
        for (int e = 0; e < NEXP; e++) { sseg[e] = s; s += scnt[e]; }
        sseg[NEXP] = s;
        int tt = 0;
        for (int e = 0; e < NEXP; e++) {
            int c = scnt[e];
            for (int off = 0; off < c; off += BM) {
                g_tile_e[tt] = e;
                g_tile_row0[tt] = sseg[e] + off;
                int rem = c - off;
                g_tile_rows[tt] = rem < BM ? rem : BM;
                tt++;
            }
        }
        for (; tt < MAXTILES; tt++) { g_tile_e[tt] = -1; g_tile_row0[tt] = 0; g_tile_rows[tt] = 0; }
        for (int r = NPAIR; r < NPAIR + 128; r++) { g_row_token[r] = 0; g_row_w[r] = 0.f; }
    }
    __syncthreads();
    for (int p = t; p < NPAIR; p += 256) {
        int e = read_eidx(idx, p);
        int slot = atomicAdd(&scur[e], 1);
        int r = sseg[e] + slot;
        g_row_token[r] = p >> 1;
        g_row_w[r] = sc[p];
    }
}

// ---------------- activation: a = silu(gate) * up (fp16 in, fp16 out) ----------------
__global__ void k_act() {
    int r = blockIdx.y;
    int j = blockIdx.x * 128 + threadIdx.x;   // grid.x = 11 -> j in [0,1408)
    size_t base = (size_t)r * N1;
    float g = __half2float(g_h16[base + j]);
    float u = __half2float(g_h16[base + EDIM + j]);
    float sv = g / (1.f + __expf(-g));
    g_a[(size_t)r * EDIM + j] = __float2half_rn(sv * u);
}

// ---------------- fused MoE GEMM (fp16 mma.sync, 3-stage cp.async) ----------------
// R16-identical structure and schedule. Single delta: the kt mainloop is
// manually unrolled by 3 so every stage index is a compile-time literal ->
// all smem offsets (ldsm, cp.async dst) fold to base+immediate, removing the
// runtime stage*offset ALU from the issue path ahead of each ldsm/mma.
template<int KIT, int LDB, bool G1>
__global__ void __launch_bounds__(256, 2) moe_gemm(float* __restrict__ out) {
    int tile = blockIdx.y;
    int te = g_tile_e[tile];
    if (te < 0) return;
    int row0  = g_tile_row0[tile];
    int trows = g_tile_rows[tile];
    int n0 = blockIdx.x * BN;
    const __half* Bexp = (G1 ? g_up16 : g_dn16) + (size_t)te * (size_t)(KIT * BK) * LDB;

    extern __shared__ __half smem[];
    uint32_t sbase = (uint32_t)__cvta_generic_to_shared(smem);
    int tid = threadIdx.x;

    // per-thread load assignments (fixed across k-iterations)
    const __half* a_src[4]; uint32_t a_dst[4];
    const __half* b_src[4]; uint32_t b_dst[4];
#pragma unroll
    for (int i = 0; i < 4; i++) {
        int cid = tid + i * 256;
        int m = cid >> 3, c = cid & 7;                          // A: 128 rows x 8 chunks(16B)
        a_dst[i] = sbase + (uint32_t)((m * 64 + ((c ^ (m & 7)) << 3)) * 2);
        if (G1) {
            int tok = g_row_token[row0 + m];                    // pad rows -> token 0, masked later
            a_src[i] = g_x16 + (size_t)tok * HID + c * 8;
        } else {
            a_src[i] = g_a + (size_t)(row0 + m) * EDIM + c * 8; // padded scratch, in-bounds
        }
        int k = cid >> 4, cn = cid & 15;                        // B: 64 rows x 16 chunks(16B)
        b_dst[i] = sbase + (uint32_t)((A_ST + k * 128 + ((cn ^ (k & 7)) << 3)) * 2);
        b_src[i] = Bexp + (size_t)k * LDB + n0 + cn * 8;
    }

    auto load_tile = [&](int stage, int kt) {
        uint32_t soff = (uint32_t)(stage * STG * 2);            // stage is a literal at call sites
        int k0 = kt * BK;
#pragma unroll
        for (int i = 0; i < 4; i++) cp16(a_dst[i] + soff, a_src[i] + k0);
#pragma unroll
        for (int i = 0; i < 4; i++) cp16(b_dst[i] + soff, b_src[i] + (size_t)k0 * LDB);
    };

    int lane = tid & 31, warp = tid >> 5;
    int wm = (warp & 3) * 32;      // 4 warps along M
    int wn = (warp >> 2) * 64;     // 2 warps along N
    int lr = lane & 15, lc = lane >> 4;

    float acc[2][8][4];
#pragma unroll
    for (int im = 0; im < 2; im++)
#pragma unroll
        for (int j = 0; j < 8; j++)
#pragma unroll
            for (int q = 0; q < 4; q++) acc[im][j][q] = 0.f;

    auto compute_stage = [&](int stage) {
        uint32_t abase = sbase + (uint32_t)(stage * STG * 2);   // literal stage -> immediate offsets
        uint32_t bbase = abase + A_ST * 2;
#pragma unroll
        for (int kk = 0; kk < 4; kk++) {                 // 4 x k16 per BK=64
            uint32_t af[2][4], bf[8][2];
#pragma unroll
            for (int im = 0; im < 2; im++) {
                int m = wm + im * 16 + lr;
                int c = kk * 2 + lc;
                ldsm4(af[im][0], af[im][1], af[im][2], af[im][3],
                      abase + (uint32_t)((m * 64 + ((c ^ (m & 7)) << 3)) * 2));
            }
#pragma unroll
            for (int jn = 0; jn < 4; jn++) {
                int k = kk * 16 + lr;
                int c = ((wn + jn * 16) >> 3) + lc;
                ldsm4t(bf[2*jn][0], bf[2*jn][1], bf[2*jn+1][0], bf[2*jn+1][1],
                       bbase + (uint32_t)((k * 128 + ((c ^ (k & 7)) << 3)) * 2));
            }
#pragma unroll
            for (int im = 0; im < 2; im++)
#pragma unroll
                for (int j = 0; j < 8; j++)
                    mma16816(acc[im][j], af[im], bf[j]);
        }
    };

    // one pipeline iteration; st / st_p2 = (st+2)%3 are literals at every call site
    auto iteration = [&](int kt, int st, int st_p2) {
        asm volatile("cp.async.wait_group 1;\n" ::: "memory");
        __syncthreads();
        if (kt + 2 < KIT) load_tile(st_p2, kt + 2);
        cp_commit();
        compute_stage(st);
    };

    // pipeline: prologue loads stages 0,1
    load_tile(0, 0); cp_commit();
    load_tile(1, 1); cp_commit();
    int kt = 0;
#pragma unroll 1
    for (; kt + 3 <= KIT; kt += 3) {
        iteration(kt,     0, 2);
        iteration(kt + 1, 1, 0);
        iteration(kt + 2, 2, 1);
    }
    if (kt < KIT)     iteration(kt,     0, 2);   // KIT%3==2: kt%3==0 here
    if (kt + 1 < KIT) iteration(kt + 1, 1, 0);

    // epilogue
    int lq = lane >> 2;
    int ln = (lane & 3) * 2;
    if (G1) {
#pragma unroll
        for (int im = 0; im < 2; im++) {
#pragma unroll
            for (int rr = 0; rr < 2; rr++) {
                int rl = wm + im * 16 + lq + rr * 8;
                if (rl < trows) {
                    size_t rowb = (size_t)(row0 + rl) * N1;
#pragma unroll
                    for (int j = 0; j < 8; j++) {
                        int n = n0 + wn + j * 8 + ln;
                        *reinterpret_cast<__half2*>(&g_h16[rowb + n]) =
                            __floats2half2_rn(acc[im][j][2*rr], acc[im][j][2*rr + 1]);
                    }
                }
            }
        }
    } else {
#pragma unroll
        for (int im = 0; im < 2; im++) {
#pragma unroll
            for (int rr = 0; rr < 2; rr++) {
                int rl = wm + im * 16 + lq + rr * 8;
                if (rl < trows) {
                    int tok = g_row_token[row0 + rl];
                    float w = g_row_w[row0 + rl];
                    float* ob = out + (size_t)tok * HID;
#pragma unroll
                    for (int j = 0; j < 8; j++) {
                        int n = n0 + wn + j * 8 + ln;
                        atomicAdd(&ob[n],     w * acc[im][j][2*rr]);
                        atomicAdd(&ob[n + 1], w * acc[im][j][2*rr + 1]);
                    }
                }
            }
        }
    }
}

// ---------------- host entry ----------------
extern "C" void kernel_launch(void* const* d_in, const int* in_sizes, int n_in,
                              void* d_out, int out_size) {
    const float* x    = (const float*)d_in[0];
    const void*  eidx = d_in[1];                 // int32 or int64 — detected on device
    const float* sc   = (const float*)d_in[2];
    const float* up   = (const float*)d_in[3];
    const float* dn   = (const float*)d_in[4];
    float*       out  = (float*)d_out;

    cudaFuncSetAttribute(moe_gemm<HID/BK,  N1,  true >, cudaFuncAttributeMaxDynamicSharedMemorySize, SMEM_BYTES);
    cudaFuncSetAttribute(moe_gemm<EDIM/BK, HID, false>, cudaFuncAttributeMaxDynamicSharedMemorySize, SMEM_BYTES);

    cudaMemsetAsync(d_out, 0, (size_t)T_TOKENS * HID * sizeof(float), 0);

    // Launch order keeps GEMM1 at the ncu capture slot.
    k_cvt_x    <<<(T_TOKENS*HID)/4/256, 256>>>((const float4*)x);        // 1
    k_cvt_up   <<<(NEXP*HID*N1) /4/256, 256>>>((const float4*)up);       // 2
    k_route_all<<<1, 256>>>((const int*)eidx, sc);                       // 3

    // GEMM1: h16 = gather(x16) @ up16[e]  (22 x 136 CTAs)                  4
    moe_gemm<HID/BK, N1, true><<<dim3(N1/BN, MAXTILES), 256, SMEM_BYTES>>>(nullptr);

    k_cvt_dn   <<<(NEXP*EDIM*HID)/4/256, 256>>>((const float4*)dn);      // 5

    // activation: a = silu(gate) * up                                      6
    k_act<<<dim3(EDIM/128, NPAIR), 128>>>();

    // GEMM2: out += w * (a @ dn16[e])  (16 x 136 CTAs)                     7
    moe_gemm<EDIM/BK, HID, false><<<dim3(HID/128, MAXTILES), 256, SMEM_BYTES>>>(out);

    (void)in_sizes; (void)n_in; (void)out_size;
}